// round 1
// baseline (speedup 1.0000x reference)
#include <cuda_runtime.h>
#include <math.h>

// Problem constants (fixed by the problem spec)
#define B_      128
#define S_      256
#define MW      21
#define VOCAB   100
#define ECHAR   50
#define EWORD   256
#define KW      5
#define T_OUT   17              // MW - KW + 1
#define NWORDS  (B_ * S_)       // 32768

// Scratch (static device globals — no allocations allowed)
__device__ float g_P[VOCAB * KW * EWORD];   // [v][k][e] : 512 KB
__device__ float g_Y[NWORDS * EWORD];       // [word][e] : 32 MB

// ---------------------------------------------------------------------------
// Kernel 1: P[v,k,e] = sum_c conv_w[e,c,k] * emb[v,c]
// grid = VOCAB blocks, 256 threads (one per e)
// ---------------------------------------------------------------------------
__global__ void precompute_P(const float* __restrict__ emb,
                             const float* __restrict__ cw) {
    __shared__ float se[ECHAR];
    const int v = blockIdx.x;
    const int e = threadIdx.x;
    if (e < ECHAR) se[e] = emb[v * ECHAR + e];
    __syncthreads();

    float a0 = 0.f, a1 = 0.f, a2 = 0.f, a3 = 0.f, a4 = 0.f;
    const float* wr = cw + e * (ECHAR * KW);
#pragma unroll 10
    for (int c = 0; c < ECHAR; c++) {
        const float ev = se[c];
        a0 += wr[c * KW + 0] * ev;
        a1 += wr[c * KW + 1] * ev;
        a2 += wr[c * KW + 2] * ev;
        a3 += wr[c * KW + 3] * ev;
        a4 += wr[c * KW + 4] * ev;
    }
    const int base = v * (KW * EWORD) + e;
    g_P[base + 0 * EWORD] = a0;
    g_P[base + 1 * EWORD] = a1;
    g_P[base + 2 * EWORD] = a2;
    g_P[base + 3 * EWORD] = a3;
    g_P[base + 4 * EWORD] = a4;
}

// ---------------------------------------------------------------------------
// Kernel 2: conv-as-table-lookup + ReLU + maxpool.
//   y[w,e] = relu( max_t ( sum_k P[char[w,t+k], k, e] ) + conv_b[e] )
// Block: 512 threads, e-slice of 64 (grid.y = 4), 256 words per block
// (grid.x = 128). P e-slice staged in 125 KB dynamic SMEM, layout
// sP[v*320 + k*64 + el] — warp-uniform word => conflict-free LDS.
// ---------------------------------------------------------------------------
__global__ void __launch_bounds__(512)
conv_max_kernel(const int* __restrict__ ps, const float* __restrict__ cb) {
    extern __shared__ float sP[];               // [VOCAB][KW][64]
    const int e0 = blockIdx.y * 64;

    // stage P slice: 32000 floats, coalesced in 64-float runs
    for (int i = threadIdx.x; i < VOCAB * KW * 64; i += 512) {
        const int v  = i / 320;
        const int r  = i - v * 320;             // k*64 + el
        const int k  = r >> 6;
        const int el = r & 63;
        sP[i] = g_P[v * (KW * EWORD) + k * EWORD + e0 + el];
    }
    __syncthreads();

    const int el = threadIdx.x & 63;
    const int wl = threadIdx.x >> 6;            // 0..7 words in flight
    const float bias = cb[e0 + el];
    const int wbase = blockIdx.x * 256;         // 32768 / 128 blocks

    for (int it = 0; it < 32; it++) {
        const int w = wbase + it * 8 + wl;
        const int* cid = ps + w * MW;

        int off[MW];
#pragma unroll
        for (int j = 0; j < MW; j++) off[j] = cid[j] * (KW * 64) + el;

        float m = -1e30f;
#pragma unroll
        for (int t = 0; t < T_OUT; t++) {
            float s = sP[off[t + 0] + 0 * 64]
                    + sP[off[t + 1] + 1 * 64]
                    + sP[off[t + 2] + 2 * 64]
                    + sP[off[t + 3] + 3 * 64]
                    + sP[off[t + 4] + 4 * 64];
            m = fmaxf(m, s);
        }
        g_Y[w * EWORD + e0 + el] = fmaxf(m + bias, 0.f);
    }
}

// ---------------------------------------------------------------------------
// Kernel 3: fused highway network (dual GEMM sharing the A tile).
//   proj = relu(Y @ Wp^T + bp); gate = sigmoid(Y @ Wg^T + bg)
//   out  = gate * proj + (1 - gate) * Y
// Tiled fp32 GEMM: BM=128, BN=64, BK=32, 256 threads, 8x4 thread tile per
// output matrix. SMEM padded to stride 33 -> conflict-free LDS/STS.
// ---------------------------------------------------------------------------
#define BM3 128
#define BN3 64
#define BK3 32

__global__ void __launch_bounds__(256)
highway_kernel(const float* __restrict__ Wp, const float* __restrict__ bp,
               const float* __restrict__ Wg, const float* __restrict__ bg,
               float* __restrict__ out) {
    __shared__ float As[BM3][BK3 + 1];
    __shared__ float Bps[BN3][BK3 + 1];
    __shared__ float Bgs[BN3][BK3 + 1];

    const int m0 = blockIdx.x * BM3;
    const int n0 = blockIdx.y * BN3;
    const int tid = threadIdx.x;
    const int tx = tid & 15;        // n direction, 0..15
    const int ty = tid >> 4;        // m direction, 0..15

    float accP[8][4];
    float accG[8][4];
#pragma unroll
    for (int i = 0; i < 8; i++)
#pragma unroll
        for (int j = 0; j < 4; j++) { accP[i][j] = 0.f; accG[i][j] = 0.f; }

    for (int k0 = 0; k0 < EWORD; k0 += BK3) {
        // A tile: 128x32 floats = 1024 float4, 4 per thread
#pragma unroll
        for (int t = 0; t < 4; t++) {
            const int f  = tid + t * 256;
            const int m  = f >> 3;
            const int c4 = (f & 7) << 2;
            const float4 v = *reinterpret_cast<const float4*>(
                &g_Y[(m0 + m) * EWORD + k0 + c4]);
            As[m][c4 + 0] = v.x; As[m][c4 + 1] = v.y;
            As[m][c4 + 2] = v.z; As[m][c4 + 3] = v.w;
        }
        // B tiles: 64x32 floats = 512 float4, 2 per thread each
#pragma unroll
        for (int t = 0; t < 2; t++) {
            const int f  = tid + t * 256;
            const int n  = f >> 3;
            const int c4 = (f & 7) << 2;
            const float4 vp = *reinterpret_cast<const float4*>(
                &Wp[(n0 + n) * EWORD + k0 + c4]);
            Bps[n][c4 + 0] = vp.x; Bps[n][c4 + 1] = vp.y;
            Bps[n][c4 + 2] = vp.z; Bps[n][c4 + 3] = vp.w;
            const float4 vg = *reinterpret_cast<const float4*>(
                &Wg[(n0 + n) * EWORD + k0 + c4]);
            Bgs[n][c4 + 0] = vg.x; Bgs[n][c4 + 1] = vg.y;
            Bgs[n][c4 + 2] = vg.z; Bgs[n][c4 + 3] = vg.w;
        }
        __syncthreads();

#pragma unroll
        for (int kk = 0; kk < BK3; kk++) {
            float a[8], bpf[4], bgf[4];
#pragma unroll
            for (int i = 0; i < 8; i++) a[i] = As[ty * 8 + i][kk];
#pragma unroll
            for (int j = 0; j < 4; j++) {
                bpf[j] = Bps[tx * 4 + j][kk];
                bgf[j] = Bgs[tx * 4 + j][kk];
            }
#pragma unroll
            for (int i = 0; i < 8; i++)
#pragma unroll
                for (int j = 0; j < 4; j++) {
                    accP[i][j] += a[i] * bpf[j];
                    accG[i][j] += a[i] * bgf[j];
                }
        }
        __syncthreads();
    }

    // Epilogue: bias, relu, sigmoid, highway combine
#pragma unroll
    for (int i = 0; i < 8; i++) {
        const int m = m0 + ty * 8 + i;
#pragma unroll
        for (int j = 0; j < 4; j++) {
            const int n = n0 + tx * 4 + j;
            const float p = fmaxf(accP[i][j] + bp[n], 0.f);
            const float z = accG[i][j] + bg[n];
            const float g = 1.f / (1.f + expf(-z));
            const float y = g_Y[m * EWORD + n];
            out[m * EWORD + n] = g * p + (1.f - g) * y;
        }
    }
}

// ---------------------------------------------------------------------------
extern "C" void kernel_launch(void* const* d_in, const int* in_sizes, int n_in,
                              void* d_out, int out_size) {
    const int*   ps  = (const int*)d_in[0];    // padded_sents int32 [B,S,MW]
    const float* emb = (const float*)d_in[1];  // [VOCAB, ECHAR]
    const float* cw  = (const float*)d_in[2];  // [EWORD, ECHAR, KW]
    const float* cb  = (const float*)d_in[3];  // [EWORD]
    const float* wp  = (const float*)d_in[4];  // [EWORD, EWORD]
    const float* bpv = (const float*)d_in[5];  // [EWORD]
    const float* wg  = (const float*)d_in[6];  // [EWORD, EWORD]
    const float* bgv = (const float*)d_in[7];  // [EWORD]
    float* out = (float*)d_out;                // [B,S,EWORD] fp32

    precompute_P<<<VOCAB, 256>>>(emb, cw);

    const int smem2 = VOCAB * KW * 64 * (int)sizeof(float);   // 128000 B
    cudaFuncSetAttribute(conv_max_kernel,
                         cudaFuncAttributeMaxDynamicSharedMemorySize, smem2);
    conv_max_kernel<<<dim3(128, 4), 512, smem2>>>(ps, cb);

    highway_kernel<<<dim3(NWORDS / BM3, EWORD / BN3), 256>>>(wp, bpv, wg, bgv, out);
}

// round 2
// speedup vs baseline: 1.1835x; 1.1835x over previous
#include <cuda_runtime.h>
#include <math.h>

// Problem constants
#define B_      128
#define S_      256
#define MW      21
#define VOCAB   100
#define ECHAR   50
#define EWORD   256
#define KW      5
#define T_OUT   17
#define NWORDS  (B_ * S_)       // 32768
#define NCAT    512             // Wp rows ++ Wg rows

// Scratch (device globals — no allocs allowed)
__device__ float g_P [VOCAB * KW * EWORD];     // [v][k][e]
__device__ float g_Y [NWORDS * EWORD];         // [w][e]  (m-major)
__device__ float g_Yt[EWORD * NWORDS];         // [e][w]  (k-major for GEMM A)
__device__ float g_Wt[EWORD * NCAT];           // [k][n_cat] transposed weights

// ---- packed f32x2 helpers ----
#define PK_FMA(d, a, b, c) \
    asm("fma.rn.f32x2 %0, %1, %2, %3;" : "=l"(d) : "l"(a), "l"(b), "l"(c))
#define PK_ADD(d, a, b) \
    asm("add.rn.f32x2 %0, %1, %2;" : "=l"(d) : "l"(a), "l"(b))
#define PK_PACK(d, lo, hi) \
    asm("mov.b64 %0, {%1, %2};" : "=l"(d) : "f"(lo), "f"(hi))
#define PK_UNPACK(lo, hi, v) \
    asm("mov.b64 {%0, %1}, %2;" : "=f"(lo), "=f"(hi) : "l"(v))

typedef unsigned long long ull;

// ---------------------------------------------------------------------------
// Kernel 0: transpose Wp/Wg into g_Wt[k][ncat]  (ncat: 0..255 = Wp, 256.. = Wg)
// ---------------------------------------------------------------------------
__global__ void transposeW(const float* __restrict__ Wp,
                           const float* __restrict__ Wg) {
    const int idx = blockIdx.x * 256 + threadIdx.x;   // 65536 elems per matrix
    const int n = idx >> 8, k = idx & 255;
    g_Wt[k * NCAT + n]         = Wp[idx];
    g_Wt[k * NCAT + 256 + n]   = Wg[idx];
}

// ---------------------------------------------------------------------------
// Kernel 1: P[v,k,e] = sum_c conv_w[e,c,k] * emb[v,c]
// grid (VOCAB, 2), 128 threads
// ---------------------------------------------------------------------------
__global__ void precompute_P(const float* __restrict__ emb,
                             const float* __restrict__ cw) {
    __shared__ float se[ECHAR];
    const int v = blockIdx.x;
    const int e = blockIdx.y * 128 + threadIdx.x;
    if (threadIdx.x < ECHAR) se[threadIdx.x] = emb[v * ECHAR + threadIdx.x];
    __syncthreads();

    float a0 = 0.f, a1 = 0.f, a2 = 0.f, a3 = 0.f, a4 = 0.f;
    const float* wr = cw + e * (ECHAR * KW);
#pragma unroll 10
    for (int c = 0; c < ECHAR; c++) {
        const float ev = se[c];
        a0 += wr[c * KW + 0] * ev;
        a1 += wr[c * KW + 1] * ev;
        a2 += wr[c * KW + 2] * ev;
        a3 += wr[c * KW + 3] * ev;
        a4 += wr[c * KW + 4] * ev;
    }
    const int base = v * (KW * EWORD) + e;
    g_P[base + 0 * EWORD] = a0;
    g_P[base + 1 * EWORD] = a1;
    g_P[base + 2 * EWORD] = a2;
    g_P[base + 3 * EWORD] = a3;
    g_P[base + 4 * EWORD] = a4;
}

// ---------------------------------------------------------------------------
// Kernel 2: conv-as-table-lookup + ReLU + maxpool, packed f32x2 adds.
// Block: 512 threads, 64-e slice (grid.y=4), 256 words (grid.x=128).
// sP: float2-viewed slice of P in SMEM; sY: 64x(256+1) result staging buffer
// so both g_Y (m-major) and g_Yt (k-major) writes are coalesced.
// ---------------------------------------------------------------------------
#define SY_STRIDE 257

__global__ void __launch_bounds__(512)
conv_max_kernel(const int* __restrict__ ps, const float* __restrict__ cb) {
    extern __shared__ float smem_c[];
    float* sP = smem_c;                             // VOCAB*KW*64 floats
    float* sY = smem_c + VOCAB * KW * 64;           // 64 * 257 floats
    const ull* sPll = (const ull*)sP;

    const int e0 = blockIdx.y * 64;
    const int w0 = blockIdx.x * 256;

    // stage P slice (coalesced 64-float runs)
    for (int i = threadIdx.x; i < VOCAB * KW * 64; i += 512) {
        const int v  = i / 320;
        const int r  = i - v * 320;
        const int k  = r >> 6;
        const int el = r & 63;
        sP[i] = g_P[v * (KW * EWORD) + k * EWORD + e0 + el];
    }
    __syncthreads();

    const int el2 = threadIdx.x & 31;               // float2 lane: e pair
    const int wl  = threadIdx.x >> 5;               // 0..15 words in flight
    const float2 bias = *(const float2*)&cb[e0 + el2 * 2];

    for (int it = 0; it < 16; it++) {
        const int wloc = it * 16 + wl;
        const int* cid = ps + (w0 + wloc) * MW;

        int off[MW];
#pragma unroll
        for (int j = 0; j < MW; j++)
            off[j] = __ldg(&cid[j]) * (KW * 32) + el2;   // float2 units

        float m0 = -1e30f, m1 = -1e30f;
#pragma unroll
        for (int t = 0; t < T_OUT; t++) {
            ull p0 = sPll[off[t + 0] + 0 * 32];
            ull p1 = sPll[off[t + 1] + 1 * 32];
            ull p2 = sPll[off[t + 2] + 2 * 32];
            ull p3 = sPll[off[t + 3] + 3 * 32];
            ull p4 = sPll[off[t + 4] + 4 * 32];
            ull s0, s1;
            PK_ADD(s0, p0, p1);
            PK_ADD(s1, p2, p3);
            PK_ADD(s0, s0, p4);
            PK_ADD(s0, s0, s1);
            float lo, hi;
            PK_UNPACK(lo, hi, s0);
            m0 = fmaxf(m0, lo);
            m1 = fmaxf(m1, hi);
        }
        const float r0 = fmaxf(m0 + bias.x, 0.f);
        const float r1 = fmaxf(m1 + bias.y, 0.f);
        sY[(el2 * 2 + 0) * SY_STRIDE + wloc] = r0;
        sY[(el2 * 2 + 1) * SY_STRIDE + wloc] = r1;
    }
    __syncthreads();

    // coalesced writeout: g_Yt (k-major)
    for (int i = threadIdx.x; i < 64 * 256; i += 512) {
        const int e = i >> 8, w = i & 255;
        g_Yt[(e0 + e) * NWORDS + w0 + w] = sY[e * SY_STRIDE + w];
    }
    // coalesced writeout: g_Y (m-major)
    for (int i = threadIdx.x; i < 64 * 256; i += 512) {
        const int w = i >> 6, e = i & 63;
        g_Y[(w0 + w) * EWORD + e0 + e] = sY[e * SY_STRIDE + w];
    }
}

// ---------------------------------------------------------------------------
// Kernel 3: fused highway dual-GEMM with packed f32x2 FMAs.
// Block tile 128m x 64n (per matrix), BK=32, 256 threads, thread tile 8m x 4n
// per matrix. All SMEM tiles k-major, LDS.128 conflict-free.
// ---------------------------------------------------------------------------
#define BM3 128
#define BN3 64
#define BK3 32
#define AS_STRIDE 132   // BM3 + 4 (keeps 16B alignment, conflict-free)
#define BS_STRIDE 68    // BN3 + 4

__global__ void __launch_bounds__(256, 2)
highway_gemm(const float* __restrict__ bp, const float* __restrict__ bg,
             float* __restrict__ out) {
    __shared__ float As [BK3 * AS_STRIDE];
    __shared__ float Bsp[BK3 * BS_STRIDE];
    __shared__ float Bsg[BK3 * BS_STRIDE];

    const int m0 = blockIdx.x * BM3;
    const int n0 = blockIdx.y * BN3;
    const int tid = threadIdx.x;
    const int tx = tid & 15;     // n-group: columns tx*4..+3
    const int ty = tid >> 4;     // m-group: rows ty*8..+7

    ull accP[8][2], accG[8][2];
#pragma unroll
    for (int i = 0; i < 8; i++)
#pragma unroll
        for (int j = 0; j < 2; j++) { accP[i][j] = 0ull; accG[i][j] = 0ull; }

    for (int k0 = 0; k0 < EWORD; k0 += BK3) {
        // A tile: 32k x 128m, from g_Yt (k-major) — coalesced, STS.128
#pragma unroll
        for (int q = 0; q < 4; q++) {
            const int idx = tid + q * 256;
            const int kk = idx >> 5;
            const int m4 = (idx & 31) << 2;
            *(float4*)&As[kk * AS_STRIDE + m4] =
                *(const float4*)&g_Yt[(k0 + kk) * NWORDS + m0 + m4];
        }
        // B tiles: 32k x 64n each, from g_Wt (k-major)
#pragma unroll
        for (int q = 0; q < 2; q++) {
            const int idx = tid + q * 256;
            const int kk = idx >> 4;
            const int n4 = (idx & 15) << 2;
            *(float4*)&Bsp[kk * BS_STRIDE + n4] =
                *(const float4*)&g_Wt[(k0 + kk) * NCAT + n0 + n4];
            *(float4*)&Bsg[kk * BS_STRIDE + n4] =
                *(const float4*)&g_Wt[(k0 + kk) * NCAT + 256 + n0 + n4];
        }
        __syncthreads();

#pragma unroll 8
        for (int kk = 0; kk < BK3; kk++) {
            const float4 a03 = *(const float4*)&As[kk * AS_STRIDE + ty * 8];
            const float4 a47 = *(const float4*)&As[kk * AS_STRIDE + ty * 8 + 4];
            ull pa[8];
            PK_PACK(pa[0], a03.x, a03.x); PK_PACK(pa[1], a03.y, a03.y);
            PK_PACK(pa[2], a03.z, a03.z); PK_PACK(pa[3], a03.w, a03.w);
            PK_PACK(pa[4], a47.x, a47.x); PK_PACK(pa[5], a47.y, a47.y);
            PK_PACK(pa[6], a47.z, a47.z); PK_PACK(pa[7], a47.w, a47.w);

            const ulonglong2 pbp = *(const ulonglong2*)&Bsp[kk * BS_STRIDE + tx * 4];
            const ulonglong2 pbg = *(const ulonglong2*)&Bsg[kk * BS_STRIDE + tx * 4];

#pragma unroll
            for (int i = 0; i < 8; i++) {
                PK_FMA(accP[i][0], pa[i], pbp.x, accP[i][0]);
                PK_FMA(accP[i][1], pa[i], pbp.y, accP[i][1]);
                PK_FMA(accG[i][0], pa[i], pbg.x, accG[i][0]);
                PK_FMA(accG[i][1], pa[i], pbg.y, accG[i][1]);
            }
        }
        __syncthreads();
    }

    // fused highway epilogue
    const int nb = n0 + tx * 4;
    const float4 bp4 = *(const float4*)&bp[nb];
    const float4 bg4 = *(const float4*)&bg[nb];

#pragma unroll
    for (int i = 0; i < 8; i++) {
        const int m = m0 + ty * 8 + i;
        const float4 y4 = *(const float4*)&g_Y[m * EWORD + nb];

        float p0, p1, p2, p3, z0, z1, z2, z3;
        PK_UNPACK(p0, p1, accP[i][0]);
        PK_UNPACK(p2, p3, accP[i][1]);
        PK_UNPACK(z0, z1, accG[i][0]);
        PK_UNPACK(z2, z3, accG[i][1]);

        p0 = fmaxf(p0 + bp4.x, 0.f);  p1 = fmaxf(p1 + bp4.y, 0.f);
        p2 = fmaxf(p2 + bp4.z, 0.f);  p3 = fmaxf(p3 + bp4.w, 0.f);
        const float g0 = 1.f / (1.f + __expf(-(z0 + bg4.x)));
        const float g1 = 1.f / (1.f + __expf(-(z1 + bg4.y)));
        const float g2 = 1.f / (1.f + __expf(-(z2 + bg4.z)));
        const float g3 = 1.f / (1.f + __expf(-(z3 + bg4.w)));

        float4 o;
        o.x = g0 * p0 + (1.f - g0) * y4.x;
        o.y = g1 * p1 + (1.f - g1) * y4.y;
        o.z = g2 * p2 + (1.f - g2) * y4.z;
        o.w = g3 * p3 + (1.f - g3) * y4.w;
        *(float4*)&out[m * EWORD + nb] = o;
    }
}

// ---------------------------------------------------------------------------
extern "C" void kernel_launch(void* const* d_in, const int* in_sizes, int n_in,
                              void* d_out, int out_size) {
    const int*   ps  = (const int*)d_in[0];
    const float* emb = (const float*)d_in[1];
    const float* cw  = (const float*)d_in[2];
    const float* cb  = (const float*)d_in[3];
    const float* wp  = (const float*)d_in[4];
    const float* bpv = (const float*)d_in[5];
    const float* wg  = (const float*)d_in[6];
    const float* bgv = (const float*)d_in[7];
    float* out = (float*)d_out;

    transposeW<<<256, 256>>>(wp, wg);
    precompute_P<<<dim3(VOCAB, 2), 128>>>(emb, cw);

    const int smem2 = (VOCAB * KW * 64 + 64 * SY_STRIDE) * (int)sizeof(float);
    cudaFuncSetAttribute(conv_max_kernel,
                         cudaFuncAttributeMaxDynamicSharedMemorySize, smem2);
    conv_max_kernel<<<dim3(128, 4), 512, smem2>>>(ps, cb);

    highway_gemm<<<dim3(NWORDS / BM3, EWORD / BN3), 256>>>(bpv, bgv, out);
}

// round 4
// speedup vs baseline: 1.4005x; 1.1834x over previous
#include <cuda_runtime.h>
#include <cuda_bf16.h>
#include <math.h>
#include <stdint.h>

// Problem constants
#define B_      128
#define S_      256
#define MW      21
#define VOCAB   100
#define ECHAR   50
#define EWORD   256
#define KW      5
#define T_OUT   17
#define NWORDS  (B_ * S_)       // 32768

// Scratch
__device__ float          g_P [VOCAB * KW * EWORD];
__device__ float          g_Y [NWORDS * EWORD];     // fp32 [w][e]
__device__ __nv_bfloat16  g_Yh[NWORDS * EWORD];     // bf16 hi split [w][k]
__device__ __nv_bfloat16  g_Yl[NWORDS * EWORD];     // bf16 lo split
// Interleaved weights: row r = 2*n + pg  (pg: 0=proj, 1=gate), [r][k]
__device__ __nv_bfloat16  g_Wh[512 * EWORD];
__device__ __nv_bfloat16  g_Wl[512 * EWORD];

typedef unsigned long long ull;

// ---- packed f32x2 helpers (conv kernel) ----
#define PK_ADD(d, a, b) \
    asm("add.rn.f32x2 %0, %1, %2;" : "=l"(d) : "l"(a), "l"(b))
#define PK_UNPACK(lo, hi, v) \
    asm("mov.b64 {%0, %1}, %2;" : "=f"(lo), "=f"(hi) : "l"(v))

__device__ __forceinline__ uint32_t smem_u32(const void* p) {
    uint32_t a;
    asm("{ .reg .u64 t; cvta.to.shared.u64 t, %1; cvt.u32.u64 %0, t; }"
        : "=r"(a) : "l"(p));
    return a;
}

// ---- warp-level mma (sm_80 baseline PTX -> HMMA on tensor pipe) ----
#define LDSM4(r, addr) \
    asm volatile("ldmatrix.sync.aligned.m8n8.x4.shared.b16 {%0,%1,%2,%3}, [%4];" \
        : "=r"((r)[0]), "=r"((r)[1]), "=r"((r)[2]), "=r"((r)[3]) : "r"(addr))

#define MMA_BF16(d, a, b0, b1) \
    asm volatile("mma.sync.aligned.m16n8k16.row.col.f32.bf16.bf16.f32 " \
        "{%0,%1,%2,%3}, {%4,%5,%6,%7}, {%8,%9}, {%0,%1,%2,%3};" \
        : "+f"((d)[0]), "+f"((d)[1]), "+f"((d)[2]), "+f"((d)[3]) \
        : "r"((a)[0]), "r"((a)[1]), "r"((a)[2]), "r"((a)[3]), \
          "r"(b0), "r"(b1))

// ---------------------------------------------------------------------------
// Kernel 0: split weights to bf16 hi/lo, interleaving proj/gate rows.
// ---------------------------------------------------------------------------
__global__ void splitW(const float* __restrict__ Wp, const float* __restrict__ Wg) {
    const int idx = blockIdx.x * 256 + threadIdx.x;   // 65536 per matrix
    const int n = idx >> 8, k = idx & 255;
    const float p = Wp[idx], g = Wg[idx];
    const __nv_bfloat16 ph = __float2bfloat16(p);
    const __nv_bfloat16 gh = __float2bfloat16(g);
    g_Wh[(2 * n + 0) * EWORD + k] = ph;
    g_Wl[(2 * n + 0) * EWORD + k] = __float2bfloat16(p - __bfloat162float(ph));
    g_Wh[(2 * n + 1) * EWORD + k] = gh;
    g_Wl[(2 * n + 1) * EWORD + k] = __float2bfloat16(g - __bfloat162float(gh));
}

// ---------------------------------------------------------------------------
// Kernel 1: P[v,k,e] = sum_c conv_w[e,c,k] * emb[v,c]
// ---------------------------------------------------------------------------
__global__ void precompute_P(const float* __restrict__ emb,
                             const float* __restrict__ cw) {
    __shared__ float se[ECHAR];
    const int v = blockIdx.x;
    const int e = blockIdx.y * 128 + threadIdx.x;
    if (threadIdx.x < ECHAR) se[threadIdx.x] = emb[v * ECHAR + threadIdx.x];
    __syncthreads();

    float a0 = 0.f, a1 = 0.f, a2 = 0.f, a3 = 0.f, a4 = 0.f;
    const float* wr = cw + e * (ECHAR * KW);
#pragma unroll 10
    for (int c = 0; c < ECHAR; c++) {
        const float ev = se[c];
        a0 += wr[c * KW + 0] * ev;
        a1 += wr[c * KW + 1] * ev;
        a2 += wr[c * KW + 2] * ev;
        a3 += wr[c * KW + 3] * ev;
        a4 += wr[c * KW + 4] * ev;
    }
    const int base = v * (KW * EWORD) + e;
    g_P[base + 0 * EWORD] = a0;
    g_P[base + 1 * EWORD] = a1;
    g_P[base + 2 * EWORD] = a2;
    g_P[base + 3 * EWORD] = a3;
    g_P[base + 4 * EWORD] = a4;
}

// ---------------------------------------------------------------------------
// Kernel 2: conv-as-table-lookup + ReLU + maxpool (packed f32x2 adds).
// Writes g_Y fp32 + bf16 hi/lo split.
// ---------------------------------------------------------------------------
#define SY_STRIDE 257

__global__ void __launch_bounds__(512)
conv_max_kernel(const int* __restrict__ ps, const float* __restrict__ cb) {
    extern __shared__ float smem_c[];
    float* sP = smem_c;                             // VOCAB*KW*64
    float* sY = smem_c + VOCAB * KW * 64;           // 64 * 257
    const ull* sPll = (const ull*)sP;

    const int e0 = blockIdx.y * 64;
    const int w0 = blockIdx.x * 256;

    for (int i = threadIdx.x; i < VOCAB * KW * 64; i += 512) {
        const int v  = i / 320;
        const int r  = i - v * 320;
        const int k  = r >> 6;
        const int el = r & 63;
        sP[i] = g_P[v * (KW * EWORD) + k * EWORD + e0 + el];
    }
    __syncthreads();

    const int el2 = threadIdx.x & 31;
    const int wl  = threadIdx.x >> 5;
    const float2 bias = *(const float2*)&cb[e0 + el2 * 2];

    for (int it = 0; it < 16; it++) {
        const int wloc = it * 16 + wl;
        const int* cid = ps + (w0 + wloc) * MW;

        int off[MW];
#pragma unroll
        for (int j = 0; j < MW; j++)
            off[j] = __ldg(&cid[j]) * (KW * 32) + el2;

        float m0 = -1e30f, m1 = -1e30f;
#pragma unroll
        for (int t = 0; t < T_OUT; t++) {
            ull p0 = sPll[off[t + 0] + 0 * 32];
            ull p1 = sPll[off[t + 1] + 1 * 32];
            ull p2 = sPll[off[t + 2] + 2 * 32];
            ull p3 = sPll[off[t + 3] + 3 * 32];
            ull p4 = sPll[off[t + 4] + 4 * 32];
            ull s0, s1;
            PK_ADD(s0, p0, p1);
            PK_ADD(s1, p2, p3);
            PK_ADD(s0, s0, p4);
            PK_ADD(s0, s0, s1);
            float lo, hi;
            PK_UNPACK(lo, hi, s0);
            m0 = fmaxf(m0, lo);
            m1 = fmaxf(m1, hi);
        }
        sY[(el2 * 2 + 0) * SY_STRIDE + wloc] = fmaxf(m0 + bias.x, 0.f);
        sY[(el2 * 2 + 1) * SY_STRIDE + wloc] = fmaxf(m1 + bias.y, 0.f);
    }
    __syncthreads();

    for (int i = threadIdx.x; i < 64 * 256; i += 512) {
        const int w = i >> 6, e = i & 63;
        const float y = sY[e * SY_STRIDE + w];
        const int gi = (w0 + w) * EWORD + e0 + e;
        g_Y[gi] = y;
        const __nv_bfloat16 yh = __float2bfloat16(y);
        g_Yh[gi] = yh;
        g_Yl[gi] = __float2bfloat16(y - __bfloat162float(yh));
    }
}

// ---------------------------------------------------------------------------
// Kernel 3: highway dual-GEMM via mma.sync bf16 3-term split + fused epilogue.
// CTA: 64 m-rows x 128 n (256 interleaved proj/gate rows). grid (512, 2).
// 8 warps: wm = wid&1 (32m), wn = wid>>1 (64 interleaved rows = 32 n).
// K chunks of 32. SMEM row stride 80B (stride/16 odd -> LDSM conflict-free).
// ---------------------------------------------------------------------------
#define RSTR    80                       // bytes per SMEM row
#define OFF_AH  0                        // 64 * 80
#define OFF_AL  5120
#define OFF_BH  10240                    // 256 * 80
#define OFF_BL  30720
#define SM3_B   51200

__global__ void __launch_bounds__(256, 2)
highway_mma(const float* __restrict__ bp, const float* __restrict__ bg,
            float* __restrict__ out) {
    extern __shared__ char sm[];
    const uint32_t smb = smem_u32(sm);

    const int tid = threadIdx.x;
    const int wid = tid >> 5;
    const int lane = tid & 31;
    const int wm = wid & 1;          // m half: wm*32
    const int wn = wid >> 1;         // interleaved-row quarter: wn*64
    const int m0 = blockIdx.x * 64;
    const int rb = blockIdx.y * 256; // interleaved-row base in g_W*

    float acc[2][8][4];
#pragma unroll
    for (int i = 0; i < 2; i++)
#pragma unroll
        for (int j = 0; j < 8; j++)
#pragma unroll
            for (int c = 0; c < 4; c++) acc[i][j][c] = 0.f;

    const int laneRow = lane & 15;
    const int laneHi  = (lane >> 4) * 16;

    for (int ch = 0; ch < 8; ch++) {
        const int kb = ch * 32;
        __syncthreads();
        // stage A (64 rows x 64B, h+l): 1 uint4 each per thread
        {
            const int r = tid >> 2, c = tid & 3;
            const int gs = (m0 + r) * EWORD + kb + c * 8;
            *(uint4*)(sm + OFF_AH + r * RSTR + c * 16) = *(const uint4*)&g_Yh[gs];
            *(uint4*)(sm + OFF_AL + r * RSTR + c * 16) = *(const uint4*)&g_Yl[gs];
        }
        // stage B (256 rows x 64B, h+l): 4 uint4 each per thread
#pragma unroll
        for (int t = 0; t < 4; t++) {
            const int idx = tid + t * 256;
            const int r = idx >> 2, c = idx & 3;
            const int gs = (rb + r) * EWORD + kb + c * 8;
            *(uint4*)(sm + OFF_BH + r * RSTR + c * 16) = *(const uint4*)&g_Wh[gs];
            *(uint4*)(sm + OFF_BL + r * RSTR + c * 16) = *(const uint4*)&g_Wl[gs];
        }
        __syncthreads();

#pragma unroll
        for (int ks = 0; ks < 2; ks++) {
            const uint32_t kboff = ks * 32 + laneHi;

            // A fragments (hi & lo), 2 m16 tiles each
            uint32_t ah[2][4], al[2][4];
#pragma unroll
            for (int mt = 0; mt < 2; mt++) {
                const uint32_t ra = (wm * 32 + mt * 16 + laneRow) * RSTR + kboff;
                LDSM4(ah[mt], smb + OFF_AH + ra);
                LDSM4(al[mt], smb + OFF_AL + ra);
            }

            // B hi fragments: 4 x4-ldmatrix -> 8 n8 tiles
            uint32_t b0[8], b1[8];
#pragma unroll
            for (int tp = 0; tp < 4; tp++) {
                uint32_t q[4];
                LDSM4(q, smb + OFF_BH + (wn * 64 + tp * 16 + laneRow) * RSTR + kboff);
                b0[2*tp] = q[0]; b0[2*tp+1] = q[1];
                b1[2*tp] = q[2]; b1[2*tp+1] = q[3];
            }
            // Ah*Bh and Al*Bh
#pragma unroll
            for (int mt = 0; mt < 2; mt++)
#pragma unroll
                for (int j = 0; j < 8; j++) {
                    MMA_BF16(acc[mt][j], ah[mt], b0[j], b1[j]);
                    MMA_BF16(acc[mt][j], al[mt], b0[j], b1[j]);
                }

            // B lo fragments (reuse regs)
#pragma unroll
            for (int tp = 0; tp < 4; tp++) {
                uint32_t q[4];
                LDSM4(q, smb + OFF_BL + (wn * 64 + tp * 16 + laneRow) * RSTR + kboff);
                b0[2*tp] = q[0]; b0[2*tp+1] = q[1];
                b1[2*tp] = q[2]; b1[2*tp+1] = q[3];
            }
            // Ah*Bl
#pragma unroll
            for (int mt = 0; mt < 2; mt++)
#pragma unroll
                for (int j = 0; j < 8; j++)
                    MMA_BF16(acc[mt][j], ah[mt], b0[j], b1[j]);
        }
    }

    // Fused highway epilogue. C frag: c0=(r=l/4, col even=proj), c1=(gate),
    // c2/c3 same at r+8. n = by*128 + wn*32 + j*4 + (lane&3).
    const int nq = blockIdx.y * 128 + wn * 32 + (lane & 3);
#pragma unroll
    for (int mt = 0; mt < 2; mt++) {
        const int mrow = m0 + wm * 32 + mt * 16 + (lane >> 2);
#pragma unroll
        for (int j = 0; j < 8; j++) {
            const int n = nq + j * 4;
            const float bpn = __ldg(&bp[n]);
            const float bgn = __ldg(&bg[n]);

            {
                const float p = fmaxf(acc[mt][j][0] + bpn, 0.f);
                const float g = 1.f / (1.f + __expf(-(acc[mt][j][1] + bgn)));
                const float y = g_Y[mrow * EWORD + n];
                out[mrow * EWORD + n] = g * p + (1.f - g) * y;
            }
            {
                const int m2 = mrow + 8;
                const float p = fmaxf(acc[mt][j][2] + bpn, 0.f);
                const float g = 1.f / (1.f + __expf(-(acc[mt][j][3] + bgn)));
                const float y = g_Y[m2 * EWORD + n];
                out[m2 * EWORD + n] = g * p + (1.f - g) * y;
            }
        }
    }
}

// ---------------------------------------------------------------------------
extern "C" void kernel_launch(void* const* d_in, const int* in_sizes, int n_in,
                              void* d_out, int out_size) {
    const int*   ps  = (const int*)d_in[0];
    const float* emb = (const float*)d_in[1];
    const float* cw  = (const float*)d_in[2];
    const float* cb  = (const float*)d_in[3];
    const float* wp  = (const float*)d_in[4];
    const float* bpv = (const float*)d_in[5];
    const float* wg  = (const float*)d_in[6];
    const float* bgv = (const float*)d_in[7];
    float* out = (float*)d_out;

    splitW<<<256, 256>>>(wp, wg);
    precompute_P<<<dim3(VOCAB, 2), 128>>>(emb, cw);

    const int smem2 = (VOCAB * KW * 64 + 64 * SY_STRIDE) * (int)sizeof(float);
    cudaFuncSetAttribute(conv_max_kernel,
                         cudaFuncAttributeMaxDynamicSharedMemorySize, smem2);
    conv_max_kernel<<<dim3(128, 4), 512, smem2>>>(ps, cb);

    cudaFuncSetAttribute(highway_mma,
                         cudaFuncAttributeMaxDynamicSharedMemorySize, SM3_B);
    highway_mma<<<dim3(NWORDS / 64, 2), 256, SM3_B>>>(bpv, bgv, out);
}

// round 5
// speedup vs baseline: 1.4850x; 1.0603x over previous
#include <cuda_runtime.h>
#include <cuda_bf16.h>
#include <math.h>
#include <stdint.h>

// Problem constants
#define B_      128
#define S_      256
#define MW      21
#define VOCAB   100
#define ECHAR   50
#define EWORD   256
#define KW      5
#define T_OUT   17
#define NWORDS  (B_ * S_)       // 32768

// Scratch
__device__ float          g_P [VOCAB * KW * EWORD];
__device__ __nv_bfloat16  g_Yh[NWORDS * EWORD];     // bf16 hi split [w][k]
__device__ __nv_bfloat16  g_Yl[NWORDS * EWORD];     // bf16 lo split
// Interleaved weights: row r = 2*n + pg (pg: 0=proj, 1=gate), [r][k]
__device__ __nv_bfloat16  g_Wh[512 * EWORD];
__device__ __nv_bfloat16  g_Wl[512 * EWORD];

typedef unsigned long long ull;

// ---- packed f32x2 helpers ----
#define PK_ADD(d, a, b) \
    asm("add.rn.f32x2 %0, %1, %2;" : "=l"(d) : "l"(a), "l"(b))
#define PK_UNPACK(lo, hi, v) \
    asm("mov.b64 {%0, %1}, %2;" : "=f"(lo), "=f"(hi) : "l"(v))

__device__ __forceinline__ uint32_t smem_u32(const void* p) {
    uint32_t a;
    asm("{ .reg .u64 t; cvta.to.shared.u64 t, %1; cvt.u32.u64 %0, t; }"
        : "=r"(a) : "l"(p));
    return a;
}

// ---- warp-level mma + cp.async (sm_80 baseline PTX) ----
#define LDSM4(r, addr) \
    asm volatile("ldmatrix.sync.aligned.m8n8.x4.shared.b16 {%0,%1,%2,%3}, [%4];" \
        : "=r"((r)[0]), "=r"((r)[1]), "=r"((r)[2]), "=r"((r)[3]) : "r"(addr))

#define MMA_BF16(d, a, b0, b1) \
    asm volatile("mma.sync.aligned.m16n8k16.row.col.f32.bf16.bf16.f32 " \
        "{%0,%1,%2,%3}, {%4,%5,%6,%7}, {%8,%9}, {%0,%1,%2,%3};" \
        : "+f"((d)[0]), "+f"((d)[1]), "+f"((d)[2]), "+f"((d)[3]) \
        : "r"((a)[0]), "r"((a)[1]), "r"((a)[2]), "r"((a)[3]), \
          "r"(b0), "r"(b1))

#define CP16(dst, src) \
    asm volatile("cp.async.cg.shared.global [%0], [%1], 16;" \
                 :: "r"(dst), "l"(src) : "memory")
#define CP_COMMIT() asm volatile("cp.async.commit_group;" ::: "memory")
#define CP_WAIT1()  asm volatile("cp.async.wait_group 1;" ::: "memory")
#define CP_WAIT0()  asm volatile("cp.async.wait_group 0;" ::: "memory")

// ---------------------------------------------------------------------------
// Kernel 0: fused init. Blocks 0..255: split W (interleaved rows).
// Blocks 256..355: precompute P[v,k,e] = sum_c conv_w[e,c,k]*emb[v,c].
// ---------------------------------------------------------------------------
__global__ void init_kernel(const float* __restrict__ Wp,
                            const float* __restrict__ Wg,
                            const float* __restrict__ emb,
                            const float* __restrict__ cw) {
    if (blockIdx.x < 256) {
        const int idx = blockIdx.x * 256 + threadIdx.x;
        const int n = idx >> 8, k = idx & 255;
        const float p = Wp[idx], g = Wg[idx];
        const __nv_bfloat16 ph = __float2bfloat16(p);
        const __nv_bfloat16 gh = __float2bfloat16(g);
        g_Wh[(2 * n + 0) * EWORD + k] = ph;
        g_Wl[(2 * n + 0) * EWORD + k] = __float2bfloat16(p - __bfloat162float(ph));
        g_Wh[(2 * n + 1) * EWORD + k] = gh;
        g_Wl[(2 * n + 1) * EWORD + k] = __float2bfloat16(g - __bfloat162float(gh));
    } else {
        __shared__ float se[ECHAR];
        const int v = blockIdx.x - 256;
        const int e = threadIdx.x;
        if (e < ECHAR) se[e] = emb[v * ECHAR + e];
        __syncthreads();

        float a0 = 0.f, a1 = 0.f, a2 = 0.f, a3 = 0.f, a4 = 0.f;
        const float* wr = cw + e * (ECHAR * KW);
#pragma unroll 10
        for (int c = 0; c < ECHAR; c++) {
            const float ev = se[c];
            a0 += wr[c * KW + 0] * ev;
            a1 += wr[c * KW + 1] * ev;
            a2 += wr[c * KW + 2] * ev;
            a3 += wr[c * KW + 3] * ev;
            a4 += wr[c * KW + 4] * ev;
        }
        const int base = v * (KW * EWORD) + e;
        g_P[base + 0 * EWORD] = a0;
        g_P[base + 1 * EWORD] = a1;
        g_P[base + 2 * EWORD] = a2;
        g_P[base + 3 * EWORD] = a3;
        g_P[base + 4 * EWORD] = a4;
    }
}

// ---------------------------------------------------------------------------
// Kernel 2: conv-as-table-lookup + ReLU + maxpool (packed f32x2 adds).
// Writes bf16 hi/lo split only (fp32 Y reconstructed as yh+yl downstream).
// ---------------------------------------------------------------------------
#define SY_STRIDE 257

__global__ void __launch_bounds__(512)
conv_max_kernel(const int* __restrict__ ps, const float* __restrict__ cb) {
    extern __shared__ float smem_c[];
    float* sP = smem_c;                             // VOCAB*KW*64
    float* sY = smem_c + VOCAB * KW * 64;           // 64 * 257
    const ull* sPll = (const ull*)sP;

    const int e0 = blockIdx.y * 64;
    const int w0 = blockIdx.x * 256;

    for (int i = threadIdx.x; i < VOCAB * KW * 64; i += 512) {
        const int v  = i / 320;
        const int r  = i - v * 320;
        const int k  = r >> 6;
        const int el = r & 63;
        sP[i] = g_P[v * (KW * EWORD) + k * EWORD + e0 + el];
    }
    __syncthreads();

    const int el2 = threadIdx.x & 31;
    const int wl  = threadIdx.x >> 5;
    const float2 bias = *(const float2*)&cb[e0 + el2 * 2];

    for (int it = 0; it < 16; it++) {
        const int wloc = it * 16 + wl;
        const int* cid = ps + (w0 + wloc) * MW;

        int off[MW];
#pragma unroll
        for (int j = 0; j < MW; j++)
            off[j] = __ldg(&cid[j]) * (KW * 32) + el2;

        float m0 = -1e30f, m1 = -1e30f;
#pragma unroll
        for (int t = 0; t < T_OUT; t++) {
            ull p0 = sPll[off[t + 0] + 0 * 32];
            ull p1 = sPll[off[t + 1] + 1 * 32];
            ull p2 = sPll[off[t + 2] + 2 * 32];
            ull p3 = sPll[off[t + 3] + 3 * 32];
            ull p4 = sPll[off[t + 4] + 4 * 32];
            ull s0, s1;
            PK_ADD(s0, p0, p1);
            PK_ADD(s1, p2, p3);
            PK_ADD(s0, s0, p4);
            PK_ADD(s0, s0, s1);
            float lo, hi;
            PK_UNPACK(lo, hi, s0);
            m0 = fmaxf(m0, lo);
            m1 = fmaxf(m1, hi);
        }
        sY[(el2 * 2 + 0) * SY_STRIDE + wloc] = fmaxf(m0 + bias.x, 0.f);
        sY[(el2 * 2 + 1) * SY_STRIDE + wloc] = fmaxf(m1 + bias.y, 0.f);
    }
    __syncthreads();

    for (int i = threadIdx.x; i < 64 * 256; i += 512) {
        const int w = i >> 6, e = i & 63;
        const float y = sY[e * SY_STRIDE + w];
        const int gi = (w0 + w) * EWORD + e0 + e;
        const __nv_bfloat16 yh = __float2bfloat16(y);
        g_Yh[gi] = yh;
        g_Yl[gi] = __float2bfloat16(y - __bfloat162float(yh));
    }
}

// ---------------------------------------------------------------------------
// Kernel 3: highway dual-GEMM, mma.sync bf16 3-term split, cp.async
// double-buffered pipeline. CTA: 64m x 128n (256 interleaved rows), 8 warps
// (2m x 4n). K chunks of 32, 2 SMEM stages.
// ---------------------------------------------------------------------------
#define RSTR    80
#define OFF_AH  0
#define OFF_AL  5120
#define OFF_BH  10240
#define OFF_BL  30720
#define STAGE_B 51200
#define SM3_B   (2 * STAGE_B)

static __device__ __forceinline__ void stage_chunk(uint32_t sb, int tid,
                                                   int m0, int rb, int kb) {
    const int r = tid >> 2, c = tid & 3;
    {
        const long gs = ((long)(m0 + r) * EWORD + kb + c * 8) * 2;
        CP16(sb + OFF_AH + r * RSTR + c * 16, (const char*)g_Yh + gs);
        CP16(sb + OFF_AL + r * RSTR + c * 16, (const char*)g_Yl + gs);
    }
#pragma unroll
    for (int q = 0; q < 4; q++) {
        const int idx = tid + q * 256;
        const int rr = idx >> 2, cc = idx & 3;
        const long gs = ((long)(rb + rr) * EWORD + kb + cc * 8) * 2;
        CP16(sb + OFF_BH + rr * RSTR + cc * 16, (const char*)g_Wh + gs);
        CP16(sb + OFF_BL + rr * RSTR + cc * 16, (const char*)g_Wl + gs);
    }
    CP_COMMIT();
}

__global__ void __launch_bounds__(256, 2)
highway_mma(const float* __restrict__ bp, const float* __restrict__ bg,
            float* __restrict__ out) {
    extern __shared__ char sm[];
    const uint32_t smb = smem_u32(sm);

    const int tid = threadIdx.x;
    const int wid = tid >> 5;
    const int lane = tid & 31;
    const int wm = wid & 1;
    const int wn = wid >> 1;
    const int m0 = blockIdx.x * 64;
    const int rb = blockIdx.y * 256;

    float acc[2][8][4];
#pragma unroll
    for (int i = 0; i < 2; i++)
#pragma unroll
        for (int j = 0; j < 8; j++)
#pragma unroll
            for (int c = 0; c < 4; c++) acc[i][j][c] = 0.f;

    const int laneRow = lane & 15;
    const int laneHi  = (lane >> 4) * 16;

    // prologue: stage chunks 0 and 1
    stage_chunk(smb + 0 * STAGE_B, tid, m0, rb, 0);
    stage_chunk(smb + 1 * STAGE_B, tid, m0, rb, 32);

#pragma unroll
    for (int ch = 0; ch < 8; ch++) {
        if (ch < 7) CP_WAIT1(); else CP_WAIT0();
        __syncthreads();
        const uint32_t st = smb + (uint32_t)(ch & 1) * STAGE_B;

#pragma unroll
        for (int ks = 0; ks < 2; ks++) {
            const uint32_t kboff = ks * 32 + laneHi;

            uint32_t ah[2][4], al[2][4];
#pragma unroll
            for (int mt = 0; mt < 2; mt++) {
                const uint32_t ra = (wm * 32 + mt * 16 + laneRow) * RSTR + kboff;
                LDSM4(ah[mt], st + OFF_AH + ra);
                LDSM4(al[mt], st + OFF_AL + ra);
            }

            uint32_t b0[8], b1[8];
#pragma unroll
            for (int tp = 0; tp < 4; tp++) {
                uint32_t q[4];
                LDSM4(q, st + OFF_BH + (wn * 64 + tp * 16 + laneRow) * RSTR + kboff);
                b0[2*tp] = q[0]; b0[2*tp+1] = q[1];
                b1[2*tp] = q[2]; b1[2*tp+1] = q[3];
            }
#pragma unroll
            for (int mt = 0; mt < 2; mt++)
#pragma unroll
                for (int j = 0; j < 8; j++) {
                    MMA_BF16(acc[mt][j], ah[mt], b0[j], b1[j]);
                    MMA_BF16(acc[mt][j], al[mt], b0[j], b1[j]);
                }

#pragma unroll
            for (int tp = 0; tp < 4; tp++) {
                uint32_t q[4];
                LDSM4(q, st + OFF_BL + (wn * 64 + tp * 16 + laneRow) * RSTR + kboff);
                b0[2*tp] = q[0]; b0[2*tp+1] = q[1];
                b1[2*tp] = q[2]; b1[2*tp+1] = q[3];
            }
#pragma unroll
            for (int mt = 0; mt < 2; mt++)
#pragma unroll
                for (int j = 0; j < 8; j++)
                    MMA_BF16(acc[mt][j], ah[mt], b0[j], b1[j]);
        }

        __syncthreads();
        if (ch + 2 < 8)
            stage_chunk(smb + (uint32_t)(ch & 1) * STAGE_B, tid, m0, rb,
                        (ch + 2) * 32);
    }

    // Fused highway epilogue; y reconstructed from the bf16 split.
    const int nq = blockIdx.y * 128 + wn * 32 + (lane & 3);
#pragma unroll
    for (int mt = 0; mt < 2; mt++) {
        const int mrow = m0 + wm * 32 + mt * 16 + (lane >> 2);
#pragma unroll
        for (int j = 0; j < 8; j++) {
            const int n = nq + j * 4;
            const float bpn = __ldg(&bp[n]);
            const float bgn = __ldg(&bg[n]);

            {
                const int gi = mrow * EWORD + n;
                const float y = __bfloat162float(g_Yh[gi])
                              + __bfloat162float(g_Yl[gi]);
                const float p = fmaxf(acc[mt][j][0] + bpn, 0.f);
                const float g = 1.f / (1.f + __expf(-(acc[mt][j][1] + bgn)));
                out[gi] = g * p + (1.f - g) * y;
            }
            {
                const int gi = (mrow + 8) * EWORD + n;
                const float y = __bfloat162float(g_Yh[gi])
                              + __bfloat162float(g_Yl[gi]);
                const float p = fmaxf(acc[mt][j][2] + bpn, 0.f);
                const float g = 1.f / (1.f + __expf(-(acc[mt][j][3] + bgn)));
                out[gi] = g * p + (1.f - g) * y;
            }
        }
    }
}

// ---------------------------------------------------------------------------
extern "C" void kernel_launch(void* const* d_in, const int* in_sizes, int n_in,
                              void* d_out, int out_size) {
    const int*   ps  = (const int*)d_in[0];
    const float* emb = (const float*)d_in[1];
    const float* cw  = (const float*)d_in[2];
    const float* cb  = (const float*)d_in[3];
    const float* wp  = (const float*)d_in[4];
    const float* bpv = (const float*)d_in[5];
    const float* wg  = (const float*)d_in[6];
    const float* bgv = (const float*)d_in[7];
    float* out = (float*)d_out;

    init_kernel<<<256 + VOCAB, 256>>>(wp, wg, emb, cw);

    const int smem2 = (VOCAB * KW * 64 + 64 * SY_STRIDE) * (int)sizeof(float);
    cudaFuncSetAttribute(conv_max_kernel,
                         cudaFuncAttributeMaxDynamicSharedMemorySize, smem2);
    conv_max_kernel<<<dim3(128, 4), 512, smem2>>>(ps, cb);

    cudaFuncSetAttribute(highway_mma,
                         cudaFuncAttributeMaxDynamicSharedMemorySize, SM3_B);
    highway_mma<<<dim3(NWORDS / 64, 2), 256, SM3_B>>>(bpv, bgv, out);
}

// round 6
// speedup vs baseline: 1.9277x; 1.2981x over previous
#include <cuda_runtime.h>
#include <cuda_bf16.h>
#include <cuda_fp16.h>
#include <math.h>
#include <stdint.h>

// Problem constants
#define B_      128
#define S_      256
#define MW      21
#define VOCAB   100
#define ECHAR   50
#define EWORD   256
#define KW      5
#define T_OUT   17
#define NWORDS  (B_ * S_)       // 32768

// Scratch
__device__ float          g_P [VOCAB * KW * EWORD];
__device__ __nv_bfloat16  g_Yh[NWORDS * EWORD];
__device__ __nv_bfloat16  g_Yl[NWORDS * EWORD];
// Interleaved weights: row r = 2*n + pg (pg: 0=proj, 1=gate), [r][k]
__device__ __nv_bfloat16  g_Wh[512 * EWORD];
__device__ __nv_bfloat16  g_Wl[512 * EWORD];

typedef unsigned long long ull;

__device__ __forceinline__ uint32_t smem_u32(const void* p) {
    uint32_t a;
    asm("{ .reg .u64 t; cvta.to.shared.u64 t, %1; cvt.u32.u64 %0, t; }"
        : "=r"(a) : "l"(p));
    return a;
}

// ---- warp-level mma + cp.async (sm_80 baseline PTX) ----
#define LDSM4(r, addr) \
    asm volatile("ldmatrix.sync.aligned.m8n8.x4.shared.b16 {%0,%1,%2,%3}, [%4];" \
        : "=r"((r)[0]), "=r"((r)[1]), "=r"((r)[2]), "=r"((r)[3]) : "r"(addr))

#define MMA_BF16(d, a, b0, b1) \
    asm volatile("mma.sync.aligned.m16n8k16.row.col.f32.bf16.bf16.f32 " \
        "{%0,%1,%2,%3}, {%4,%5,%6,%7}, {%8,%9}, {%0,%1,%2,%3};" \
        : "+f"((d)[0]), "+f"((d)[1]), "+f"((d)[2]), "+f"((d)[3]) \
        : "r"((a)[0]), "r"((a)[1]), "r"((a)[2]), "r"((a)[3]), \
          "r"(b0), "r"(b1))

#define CP16(dst, src) \
    asm volatile("cp.async.cg.shared.global [%0], [%1], 16;" \
                 :: "r"(dst), "l"(src) : "memory")
#define CP_COMMIT() asm volatile("cp.async.commit_group;" ::: "memory")
#define CP_WAIT1()  asm volatile("cp.async.wait_group 1;" ::: "memory")
#define CP_WAIT0()  asm volatile("cp.async.wait_group 0;" ::: "memory")

// ---------------------------------------------------------------------------
// Kernel 1: P[v,k,e] — block per e, everything staged in SMEM coalesced.
// grid 256, 512 threads.
// ---------------------------------------------------------------------------
__global__ void __launch_bounds__(512)
precomputeP(const float* __restrict__ emb, const float* __restrict__ cw) {
    __shared__ float s_emb[VOCAB * ECHAR];   // 20 KB
    __shared__ float s_cw[ECHAR * KW];       // 1 KB
    const int e = blockIdx.x;
    const int tid = threadIdx.x;

    for (int i = tid; i < VOCAB * ECHAR; i += 512) s_emb[i] = emb[i];
    if (tid < ECHAR * KW) s_cw[tid] = cw[e * (ECHAR * KW) + tid];
    __syncthreads();

    if (tid < VOCAB * KW) {
        const int v = tid / KW;
        const int k = tid - v * KW;
        float a = 0.f;
#pragma unroll 10
        for (int c = 0; c < ECHAR; c++)
            a += s_cw[c * KW + k] * s_emb[v * ECHAR + c];
        g_P[v * (KW * EWORD) + k * EWORD + e] = a;
    }
}

// ---------------------------------------------------------------------------
// Kernel 2: conv-as-table-lookup + ReLU + maxpool, fp16 P table in SMEM.
// grid (128, 5): y<4 = conv slices; y==4 = W-split plane (rides free).
// ---------------------------------------------------------------------------
#define SY_STRIDE 257

__global__ void __launch_bounds__(512)
conv_max_kernel(const int* __restrict__ ps, const float* __restrict__ cb,
                const float* __restrict__ Wp, const float* __restrict__ Wg) {
    const int tid = threadIdx.x;

    if (blockIdx.y == 4) {          // W split: 512 elems per block
        const int idx = blockIdx.x * 512 + tid;
        const int n = idx >> 8, k = idx & 255;
        const float p = Wp[idx], g = Wg[idx];
        const __nv_bfloat16 ph = __float2bfloat16(p);
        const __nv_bfloat16 gh = __float2bfloat16(g);
        g_Wh[(2 * n + 0) * EWORD + k] = ph;
        g_Wl[(2 * n + 0) * EWORD + k] = __float2bfloat16(p - __bfloat162float(ph));
        g_Wh[(2 * n + 1) * EWORD + k] = gh;
        g_Wl[(2 * n + 1) * EWORD + k] = __float2bfloat16(g - __bfloat162float(gh));
        return;
    }

    extern __shared__ char smraw[];
    __half2* sPh = (__half2*)smraw;                       // VOCAB*KW*32 half2
    float*   sY  = (float*)(smraw + VOCAB * KW * 32 * 4); // 64*257 floats

    const int e0 = blockIdx.y * 64;
    const int w0 = blockIdx.x * 256;

    // stage P slice as half2 (pair = 2 consecutive e)
    for (int i = tid; i < VOCAB * KW * 32; i += 512) {
        const int v  = i / 160;
        const int r  = i - v * 160;
        const int k  = r >> 5;
        const int ep = r & 31;
        const float2 f = *(const float2*)&g_P[v * (KW * EWORD) + k * EWORD
                                              + e0 + ep * 2];
        sPh[i] = __float22half2_rn(f);
    }
    __syncthreads();

    const int el2 = tid & 31;               // e-pair lane
    const int wl  = tid >> 5;               // warp id = word lane
    const float2 bias = *(const float2*)&cb[e0 + el2 * 2];

    for (int it = 0; it < 16; it++) {
        const int wloc = it * 16 + wl;
        const int* cid = ps + (w0 + wloc) * MW;

        int off[MW];
#pragma unroll
        for (int j = 0; j < MW; j++)
            off[j] = __ldg(&cid[j]) * (KW * 32) + el2;

        float m0 = -1e30f, m1 = -1e30f;
#pragma unroll
        for (int t = 0; t < T_OUT; t++) {
            const __half2 u0 = sPh[off[t + 0] + 0 * 32];
            const __half2 u1 = sPh[off[t + 1] + 1 * 32];
            const __half2 u2 = sPh[off[t + 2] + 2 * 32];
            const __half2 u3 = sPh[off[t + 3] + 3 * 32];
            const __half2 u4 = sPh[off[t + 4] + 4 * 32];
            // one fp16 add level, rest fp32
            const __half2 s01 = __hadd2(u0, u1);
            const __half2 s23 = __hadd2(u2, u3);
            const float2 f01 = __half22float2(s01);
            const float2 f23 = __half22float2(s23);
            const float2 f4  = __half22float2(u4);
            m0 = fmaxf(m0, f01.x + f23.x + f4.x);
            m1 = fmaxf(m1, f01.y + f23.y + f4.y);
        }
        sY[(el2 * 2 + 0) * SY_STRIDE + wloc] = fmaxf(m0 + bias.x, 0.f);
        sY[(el2 * 2 + 1) * SY_STRIDE + wloc] = fmaxf(m1 + bias.y, 0.f);
    }
    __syncthreads();

    for (int i = tid; i < 64 * 256; i += 512) {
        const int w = i >> 6, e = i & 63;
        const float y = sY[e * SY_STRIDE + w];
        const int gi = (w0 + w) * EWORD + e0 + e;
        const __nv_bfloat16 yh = __float2bfloat16(y);
        g_Yh[gi] = yh;
        g_Yl[gi] = __float2bfloat16(y - __bfloat162float(yh));
    }
}

// ---------------------------------------------------------------------------
// Kernel 3: highway dual-GEMM, mma.sync bf16 3-term split, cp.async
// double-buffered pipeline (unchanged from R5 pass).
// ---------------------------------------------------------------------------
#define RSTR    80
#define OFF_AH  0
#define OFF_AL  5120
#define OFF_BH  10240
#define OFF_BL  30720
#define STAGE_B 51200
#define SM3_B   (2 * STAGE_B)

static __device__ __forceinline__ void stage_chunk(uint32_t sb, int tid,
                                                   int m0, int rb, int kb) {
    const int r = tid >> 2, c = tid & 3;
    {
        const long gs = ((long)(m0 + r) * EWORD + kb + c * 8) * 2;
        CP16(sb + OFF_AH + r * RSTR + c * 16, (const char*)g_Yh + gs);
        CP16(sb + OFF_AL + r * RSTR + c * 16, (const char*)g_Yl + gs);
    }
#pragma unroll
    for (int q = 0; q < 4; q++) {
        const int idx = tid + q * 256;
        const int rr = idx >> 2, cc = idx & 3;
        const long gs = ((long)(rb + rr) * EWORD + kb + cc * 8) * 2;
        CP16(sb + OFF_BH + rr * RSTR + cc * 16, (const char*)g_Wh + gs);
        CP16(sb + OFF_BL + rr * RSTR + cc * 16, (const char*)g_Wl + gs);
    }
    CP_COMMIT();
}

__global__ void __launch_bounds__(256, 2)
highway_mma(const float* __restrict__ bp, const float* __restrict__ bg,
            float* __restrict__ out) {
    extern __shared__ char sm[];
    const uint32_t smb = smem_u32(sm);

    const int tid = threadIdx.x;
    const int wid = tid >> 5;
    const int lane = tid & 31;
    const int wm = wid & 1;
    const int wn = wid >> 1;
    const int m0 = blockIdx.x * 64;
    const int rb = blockIdx.y * 256;

    float acc[2][8][4];
#pragma unroll
    for (int i = 0; i < 2; i++)
#pragma unroll
        for (int j = 0; j < 8; j++)
#pragma unroll
            for (int c = 0; c < 4; c++) acc[i][j][c] = 0.f;

    const int laneRow = lane & 15;
    const int laneHi  = (lane >> 4) * 16;

    stage_chunk(smb + 0 * STAGE_B, tid, m0, rb, 0);
    stage_chunk(smb + 1 * STAGE_B, tid, m0, rb, 32);

#pragma unroll
    for (int ch = 0; ch < 8; ch++) {
        if (ch < 7) CP_WAIT1(); else CP_WAIT0();
        __syncthreads();
        const uint32_t st = smb + (uint32_t)(ch & 1) * STAGE_B;

#pragma unroll
        for (int ks = 0; ks < 2; ks++) {
            const uint32_t kboff = ks * 32 + laneHi;

            uint32_t ah[2][4], al[2][4];
#pragma unroll
            for (int mt = 0; mt < 2; mt++) {
                const uint32_t ra = (wm * 32 + mt * 16 + laneRow) * RSTR + kboff;
                LDSM4(ah[mt], st + OFF_AH + ra);
                LDSM4(al[mt], st + OFF_AL + ra);
            }

            uint32_t b0[8], b1[8];
#pragma unroll
            for (int tp = 0; tp < 4; tp++) {
                uint32_t q[4];
                LDSM4(q, st + OFF_BH + (wn * 64 + tp * 16 + laneRow) * RSTR + kboff);
                b0[2*tp] = q[0]; b0[2*tp+1] = q[1];
                b1[2*tp] = q[2]; b1[2*tp+1] = q[3];
            }
#pragma unroll
            for (int mt = 0; mt < 2; mt++)
#pragma unroll
                for (int j = 0; j < 8; j++) {
                    MMA_BF16(acc[mt][j], ah[mt], b0[j], b1[j]);
                    MMA_BF16(acc[mt][j], al[mt], b0[j], b1[j]);
                }

#pragma unroll
            for (int tp = 0; tp < 4; tp++) {
                uint32_t q[4];
                LDSM4(q, st + OFF_BL + (wn * 64 + tp * 16 + laneRow) * RSTR + kboff);
                b0[2*tp] = q[0]; b0[2*tp+1] = q[1];
                b1[2*tp] = q[2]; b1[2*tp+1] = q[3];
            }
#pragma unroll
            for (int mt = 0; mt < 2; mt++)
#pragma unroll
                for (int j = 0; j < 8; j++)
                    MMA_BF16(acc[mt][j], ah[mt], b0[j], b1[j]);
        }

        __syncthreads();
        if (ch + 2 < 8)
            stage_chunk(smb + (uint32_t)(ch & 1) * STAGE_B, tid, m0, rb,
                        (ch + 2) * 32);
    }

    const int nq = blockIdx.y * 128 + wn * 32 + (lane & 3);
#pragma unroll
    for (int mt = 0; mt < 2; mt++) {
        const int mrow = m0 + wm * 32 + mt * 16 + (lane >> 2);
#pragma unroll
        for (int j = 0; j < 8; j++) {
            const int n = nq + j * 4;
            const float bpn = __ldg(&bp[n]);
            const float bgn = __ldg(&bg[n]);

            {
                const int gi = mrow * EWORD + n;
                const float y = __bfloat162float(g_Yh[gi])
                              + __bfloat162float(g_Yl[gi]);
                const float p = fmaxf(acc[mt][j][0] + bpn, 0.f);
                const float g = 1.f / (1.f + __expf(-(acc[mt][j][1] + bgn)));
                out[gi] = g * p + (1.f - g) * y;
            }
            {
                const int gi = (mrow + 8) * EWORD + n;
                const float y = __bfloat162float(g_Yh[gi])
                              + __bfloat162float(g_Yl[gi]);
                const float p = fmaxf(acc[mt][j][2] + bpn, 0.f);
                const float g = 1.f / (1.f + __expf(-(acc[mt][j][3] + bgn)));
                out[gi] = g * p + (1.f - g) * y;
            }
        }
    }
}

// ---------------------------------------------------------------------------
extern "C" void kernel_launch(void* const* d_in, const int* in_sizes, int n_in,
                              void* d_out, int out_size) {
    const int*   ps  = (const int*)d_in[0];
    const float* emb = (const float*)d_in[1];
    const float* cw  = (const float*)d_in[2];
    const float* cb  = (const float*)d_in[3];
    const float* wp  = (const float*)d_in[4];
    const float* bpv = (const float*)d_in[5];
    const float* wg  = (const float*)d_in[6];
    const float* bgv = (const float*)d_in[7];
    float* out = (float*)d_out;

    precomputeP<<<EWORD, 512>>>(emb, cw);

    const int smem2 = VOCAB * KW * 32 * 4 + 64 * SY_STRIDE * 4;   // ~130 KB
    cudaFuncSetAttribute(conv_max_kernel,
                         cudaFuncAttributeMaxDynamicSharedMemorySize, smem2);
    conv_max_kernel<<<dim3(128, 5), 512, smem2>>>(ps, cb, wp, wg);

    cudaFuncSetAttribute(highway_mma,
                         cudaFuncAttributeMaxDynamicSharedMemorySize, SM3_B);
    highway_mma<<<dim3(NWORDS / 64, 2), 256, SM3_B>>>(bpv, bgv, out);
}